// round 1
// baseline (speedup 1.0000x reference)
#include <cuda_runtime.h>
#include <cstdint>

// Problem dims (fixed by the dataset's setup_inputs)
#define B_   16
#define C_   128
#define H_   56
#define W_   56
#define HW_  (H_ * W_)          // 3136 (multiple of 32 -> warps never straddle (b,c))
#define TOTAL_ (B_ * C_ * HW_)  // 6,422,528

// Map float bits to an order-preserving unsigned (ascending)
__device__ __forceinline__ unsigned fmap(float v) {
    unsigned u = __float_as_uint(v);
    return u ^ (((unsigned)((int)u >> 31)) | 0x80000000u);
}

__device__ __forceinline__ float funmap(unsigned u) {
    // inverse of fmap
    return __uint_as_float(u ^ ((u & 0x80000000u) ? 0x80000000u : 0xFFFFFFFFu));
}

__global__ __launch_bounds__(256, 8)
void rrsvm_kernel(const float* __restrict__ x,
                  const float* __restrict__ s,
                  float* __restrict__ vout,
                  float* __restrict__ idxout) {
    // Per-warp staging buffer for coalesced index writes: 8 warps x (32 lanes * 9 ranks)
    __shared__ float stage[8][288];

    const int t = blockIdx.x * blockDim.x + threadIdx.x;   // exact grid, t < TOTAL_
    const int bc  = t / HW_;
    const int rem = t - bc * HW_;
    const int y   = rem / W_;
    const int xx  = rem - y * W_;

    const float* __restrict__ xb = x + (size_t)bc * HW_;

    // Build 9 strict-total-order keys: (mapped_value << 4) | (8 - k).
    // Descending sort of keys == stable descending sort by value with
    // ascending original-index tie-break (matches jnp.argsort(-p) stable).
    unsigned long long key[9];
#pragma unroll
    for (int dy = 0; dy < 3; dy++) {
        const int yy = y + dy - 1;
        const bool yok = ((unsigned)yy < (unsigned)H_);
#pragma unroll
        for (int dx = 0; dx < 3; dx++) {
            const int xc = xx + dx - 1;
            const int k = dy * 3 + dx;
            float v = 0.0f;
            if (yok && ((unsigned)xc < (unsigned)W_))
                v = __ldg(xb + yy * W_ + xc);
            key[k] = ((unsigned long long)fmap(v) << 4) | (unsigned)(8 - k);
        }
    }

    // Optimal 9-element sorting network (25 comparators), descending
#define CE(i, j)                                                     \
    {                                                                \
        if (key[j] > key[i]) {                                       \
            unsigned long long _t = key[i];                          \
            key[i] = key[j];                                         \
            key[j] = _t;                                             \
        }                                                            \
    }
    CE(0,3) CE(1,7) CE(2,5) CE(4,8)
    CE(0,7) CE(2,4) CE(3,8) CE(5,6)
    CE(0,2) CE(1,3) CE(4,5) CE(7,8)
    CE(1,4) CE(3,6) CE(5,7)
    CE(0,1) CE(2,4) CE(3,5) CE(6,8)
    CE(2,3) CE(4,5) CE(6,7)
    CE(1,2) CE(3,4) CE(5,6)
#undef CE

    const int c = bc & (C_ - 1);            // bc = b*C + c, C_=128 power of 2
    const float* __restrict__ sc = s + c * 9;

    const int warp = threadIdx.x >> 5;
    const int lane = threadIdx.x & 31;

    float acc = 0.0f;
#pragma unroll
    for (int r = 0; r < 9; r++) {
        const float v = funmap((unsigned)(key[r] >> 4));
        acc = fmaf(v, __ldg(sc + r), acc);
        if (idxout)
            stage[warp][lane * 9 + r] = (float)(8 - (int)(key[r] & 0xFull));
    }

    if (vout)
        vout[t] = acc;

    if (idxout) {
        __syncwarp();
        // warp's 32 pixels own a contiguous 288-float span of idxout
        const size_t base = (size_t)(t - lane) * 9;
#pragma unroll
        for (int j = 0; j < 9; j++)
            idxout[base + lane + 32 * j] = stage[warp][lane + 32 * j];
    }
}

extern "C" void kernel_launch(void* const* d_in, const int* in_sizes, int n_in,
                              void* d_out, int out_size) {
    const float* x = (const float*)d_in[0];
    const float* s = (const float*)d_in[1];

    float* vout = (float*)d_out;
    float* idxout = nullptr;

    // Reference returns (out[B,C,H,W], indices[B,C,H,W,9]).
    // Handle the plausible flattened-output conventions:
    if (out_size >= 10 * TOTAL_) {
        idxout = (float*)d_out + TOTAL_;          // [out | indices] concatenated
    } else if (out_size == 9 * TOTAL_) {
        idxout = (float*)d_out;                    // indices only
        vout = nullptr;
    }
    // else: values only (out_size == TOTAL_)

    const int threads = 256;
    const int blocks = TOTAL_ / threads;           // exact: 25088
    rrsvm_kernel<<<blocks, threads>>>(x, s, vout, idxout);
}

// round 2
// speedup vs baseline: 1.6974x; 1.6974x over previous
#include <cuda_runtime.h>
#include <cstdint>

// Problem dims (fixed by the dataset's setup_inputs)
#define B_   16
#define C_   128
#define H_   56
#define W_   56
#define HW_  (H_ * W_)          // 3136 (multiple of 32 -> warps never straddle (b,c))
#define TOTAL_ (B_ * C_ * HW_)  // 6,422,528

__global__ __launch_bounds__(256)
void rrsvm_kernel(const float* __restrict__ x,
                  const float* __restrict__ s,
                  float* __restrict__ vout,
                  float* __restrict__ idxout) {
    // Per-warp staging for coalesced index writes: 8 warps x (32 lanes * 9 ranks)
    __shared__ float stage[8][288];
    // Per-warp copy of this channel's 9 rank weights
    __shared__ float ssm[8][9];

    const int t    = blockIdx.x * blockDim.x + threadIdx.x;  // exact grid
    const int warp = threadIdx.x >> 5;
    const int lane = threadIdx.x & 31;

    const int bc  = t / HW_;
    const int rem = t - bc * HW_;
    const int y   = rem / W_;
    const int xx  = rem - y * W_;

    // Whole warp shares one (b,c): load s[c] into the warp's smem table.
    const int c = bc & (C_ - 1);            // bc = b*C + c, C power of 2
    if (lane < 9)
        ssm[warp][lane] = __ldg(s + c * 9 + lane);
    __syncwarp();

    const float* __restrict__ xb = x + (size_t)bc * HW_;

    // Gather the 3x3 window (zero padding)
    float v[9];
#pragma unroll
    for (int dy = 0; dy < 3; dy++) {
        const int yy  = y + dy - 1;
        const bool yok = ((unsigned)yy < (unsigned)H_);
#pragma unroll
        for (int dx = 0; dx < 3; dx++) {
            const int xc = xx + dx - 1;
            float val = 0.0f;
            if (yok && ((unsigned)xc < (unsigned)W_))
                val = __ldg(xb + yy * W_ + xc);
            v[dy * 3 + dx] = val;
        }
    }

    // Rank of each element in stable-descending order:
    // element i precedes j (i<j) iff v[i] >= v[j]  (ties -> lower index first,
    // exactly matching stable jnp.argsort(-p)).
    int rank[9];
#pragma unroll
    for (int i = 0; i < 9; i++) rank[i] = 0;
#pragma unroll
    for (int i = 0; i < 9; i++) {
#pragma unroll
        for (int j = i + 1; j < 9; j++) {
            if (v[i] >= v[j]) rank[j]++;
            else              rank[i]++;
        }
    }

    // Value output: sum_k v[k] * s_c[rank[k]]  (gather s via conflict-free LDS)
    // Index output: slot rank[k] gets original index k (scatter into smem stage)
    float acc = 0.0f;
#pragma unroll
    for (int k = 0; k < 9; k++) {
        acc = fmaf(v[k], ssm[warp][rank[k]], acc);
        stage[warp][lane * 9 + rank[k]] = (float)k;   // constant payload, no I2F
    }

    if (vout)
        vout[t] = acc;

    __syncwarp();
    if (idxout) {
        // warp's 32 pixels own a contiguous 288-float span of idxout -> 9 x 128B stores
        const size_t base = (size_t)(t - lane) * 9;
#pragma unroll
        for (int j = 0; j < 9; j++)
            idxout[base + lane + 32 * j] = stage[warp][lane + 32 * j];
    }
}

extern "C" void kernel_launch(void* const* d_in, const int* in_sizes, int n_in,
                              void* d_out, int out_size) {
    const float* x = (const float*)d_in[0];
    const float* s = (const float*)d_in[1];

    float* vout   = (float*)d_out;
    float* idxout = nullptr;

    // Reference returns (out[B,C,H,W], indices[B,C,H,W,9]); harness concatenates.
    if (out_size >= 10 * TOTAL_) {
        idxout = (float*)d_out + TOTAL_;   // [out | indices]
    } else if (out_size == 9 * TOTAL_) {
        idxout = (float*)d_out;            // indices only
        vout = nullptr;
    }

    const int threads = 256;
    const int blocks  = TOTAL_ / threads;  // exact: 25088
    rrsvm_kernel<<<blocks, threads>>>(x, s, vout, idxout);
}